// round 13
// baseline (speedup 1.0000x reference)
#include <cuda_runtime.h>
#include <cuda_bf16.h>
#include <cuda_fp16.h>
#include <cstdint>

// GCN layer: out = ReLU( segment_sum(feature[src], dst) @ W^T + b )
// N=100000, E=1.6M, 128 feats, fp32. src/dst int32.
//
// R13 = R11 (best: fp16 Y, GEMM fork, warp-per-node unroll-4 gather,
// single-pass scan, no memset) + W pre-split into packed bf16 hi/lo
// (wsplit kernel on s2) so the GEMM's B fragments are plain LDG.32s
// instead of per-block float loads + split ALU. R12's half-warp gather
// reverted (regressed +5.9us).

#define N_FEATS   128
#define MAX_NODES 100000
#define MAX_EDGES 1600000
#define SCAN_BLK  1024
#define N_SCAN_BLKS ((MAX_NODES + SCAN_BLK - 1) / SCAN_BLK)   // 98

__device__ __half   g_y[MAX_NODES * N_FEATS];  // Y = feat @ W^T (fp16)
__device__ int      g_deg[MAX_NODES];          // zero on entry (static/fill)
__device__ int      g_off[MAX_NODES + 1];
__device__ int      g_bsum[N_SCAN_BLKS];
__device__ int      g_boff[N_SCAN_BLKS];
__device__ int      g_rank[MAX_EDGES];
__device__ int      g_edge_src[MAX_EDGES];
__device__ int      g_scan_done;               // ticket; reset by last block
__device__ uint32_t g_Whi[128 * 64];           // W hi, bf16x2 pairs [n][j]
__device__ uint32_t g_Wlo[128 * 64];           // W lo, bf16x2 pairs [n][j]

// ---------------------------------------------------------------------------
// exact split: x = hi(bf16 trunc) + lo(bf16 rn); packs a pair into bf16x2.
// ---------------------------------------------------------------------------
__device__ __forceinline__ void split2(float a, float b,
                                       uint32_t& hi, uint32_t& lo)
{
    uint32_t ba = __float_as_uint(a), bb = __float_as_uint(b);
    uint32_t ha = ba & 0xffff0000u,   hb = bb & 0xffff0000u;
    hi = (ha >> 16) | hb;
    float la = a - __uint_as_float(ha);
    float lb = b - __uint_as_float(hb);
    asm("cvt.rn.bf16x2.f32 %0, %2, %1;" : "=r"(lo) : "f"(la), "f"(lb));
}

#define MMA16816(d, a, b)                                                     \
    asm volatile(                                                             \
        "mma.sync.aligned.m16n8k16.row.col.f32.bf16.bf16.f32 "               \
        "{%0,%1,%2,%3}, {%4,%5,%6,%7}, {%8,%9}, {%0,%1,%2,%3};"              \
        : "+f"((d)[0]), "+f"((d)[1]), "+f"((d)[2]), "+f"((d)[3])              \
        : "r"((a)[0]), "r"((a)[1]), "r"((a)[2]), "r"((a)[3]),                 \
          "r"((b)[0]), "r"((b)[1]))

// ---------------------------------------------------------------------------
// wsplit: W (128x128 fp32) -> packed bf16x2 hi/lo pair arrays, once.
// ---------------------------------------------------------------------------
__global__ void __launch_bounds__(256) wsplit_kernel(
    const float* __restrict__ W)
{
    const int i = blockIdx.x * blockDim.x + threadIdx.x;   // 0..8191
    if (i < 128 * 64) {
        const float2 w2 = reinterpret_cast<const float2*>(W)[i];
        uint32_t h, l;
        split2(w2.x, w2.y, h, l);
        g_Whi[i] = h;
        g_Wlo[i] = l;
    }
}

// ---------------------------------------------------------------------------
// GEMM: Y = feat @ W^T (fp16 out). Block 256 thr; tile 128 rows x 128 cols.
// bf16 hi/lo split, 3 MMA combos, fp32 accum. B fragments come prepacked
// from g_Whi/g_Wlo (no per-block B split work).
// ---------------------------------------------------------------------------
__global__ void __launch_bounds__(256) gemm_mma_kernel(
    const float* __restrict__ feat,   // [M, 128]
    int M)
{
    const int tid  = threadIdx.x;
    const int wid  = tid >> 5;
    const int lane = tid & 31;
    const int g    = lane >> 2;
    const int t    = lane & 3;

    const int rbase = blockIdx.x * 128 + (wid >> 1) * 32;
    const int cbase = (wid & 1) * 64;

    const float* arow[2][2];
    #pragma unroll
    for (int mt = 0; mt < 2; mt++) {
        int rlo = rbase + mt * 16 + g;
        int rhi = rlo + 8;
        if (rlo > M - 1) rlo = M - 1;
        if (rhi > M - 1) rhi = M - 1;
        arow[mt][0] = feat + (size_t)rlo * N_FEATS;
        arow[mt][1] = feat + (size_t)rhi * N_FEATS;
    }

    float acc[2][8][4];
    #pragma unroll
    for (int mt = 0; mt < 2; mt++)
        #pragma unroll
        for (int nt = 0; nt < 8; nt++)
            #pragma unroll
            for (int q = 0; q < 4; q++)
                acc[mt][nt][q] = 0.f;

    #pragma unroll 2
    for (int ks = 0; ks < 8; ks++) {
        const int k0 = ks * 16;
        const int jp = (k0 >> 1) + t;         // B pair index for this thread

        uint32_t Ah[2][4], Al[2][4];
        #pragma unroll
        for (int mt = 0; mt < 2; mt++) {
            const float2 a0 = *reinterpret_cast<const float2*>(
                arow[mt][0] + k0 + 2 * t);
            const float2 a1 = *reinterpret_cast<const float2*>(
                arow[mt][1] + k0 + 2 * t);
            const float2 a2 = *reinterpret_cast<const float2*>(
                arow[mt][0] + k0 + 2 * t + 8);
            const float2 a3 = *reinterpret_cast<const float2*>(
                arow[mt][1] + k0 + 2 * t + 8);
            split2(a0.x, a0.y, Ah[mt][0], Al[mt][0]);
            split2(a1.x, a1.y, Ah[mt][1], Al[mt][1]);
            split2(a2.x, a2.y, Ah[mt][2], Al[mt][2]);
            split2(a3.x, a3.y, Ah[mt][3], Al[mt][3]);
        }

        #pragma unroll
        for (int nt = 0; nt < 8; nt++) {
            const int n = cbase + nt * 8 + g;
            uint32_t Bh[2], Bl[2];
            Bh[0] = __ldg(&g_Whi[n * 64 + jp]);
            Bh[1] = __ldg(&g_Whi[n * 64 + jp + 4]);
            Bl[0] = __ldg(&g_Wlo[n * 64 + jp]);
            Bl[1] = __ldg(&g_Wlo[n * 64 + jp + 4]);

            #pragma unroll
            for (int mt = 0; mt < 2; mt++) {
                MMA16816(acc[mt][nt], Ah[mt], Bh);
                MMA16816(acc[mt][nt], Ah[mt], Bl);
                MMA16816(acc[mt][nt], Al[mt], Bh);
            }
        }
    }

    #pragma unroll
    for (int mt = 0; mt < 2; mt++) {
        const int rlo = rbase + mt * 16 + g;
        const int rhi = rlo + 8;
        #pragma unroll
        for (int nt = 0; nt < 8; nt++) {
            const int col = cbase + nt * 8 + 2 * t;
            if (rlo < M)
                *reinterpret_cast<__half2*>(g_y + (size_t)rlo * N_FEATS + col) =
                    __floats2half2_rn(acc[mt][nt][0], acc[mt][nt][1]);
            if (rhi < M)
                *reinterpret_cast<__half2*>(g_y + (size_t)rhi * N_FEATS + col) =
                    __floats2half2_rn(acc[mt][nt][2], acc[mt][nt][3]);
        }
    }
}

// ======================= CSR build =========================================
__global__ void __launch_bounds__(256) hist_rank_kernel(
    const int* __restrict__ dst, int n_edges)
{
    const int tid    = blockIdx.x * blockDim.x + threadIdx.x;
    const int stride = gridDim.x * blockDim.x;
    const int n4     = n_edges >> 2;

    for (int e4 = tid; e4 < n4; e4 += stride) {
        const int4 d = reinterpret_cast<const int4*>(dst)[e4];
        int4 r;
        r.x = atomicAdd(&g_deg[d.x], 1);
        r.y = atomicAdd(&g_deg[d.y], 1);
        r.z = atomicAdd(&g_deg[d.z], 1);
        r.w = atomicAdd(&g_deg[d.w], 1);
        reinterpret_cast<int4*>(g_rank)[e4] = r;
    }
    for (int e = (n4 << 2) + tid; e < n_edges; e += stride)
        g_rank[e] = atomicAdd(&g_deg[dst[e]], 1);
}

// single-pass scan: per-block exclusive scan of g_deg -> g_off + block sums;
// the LAST block to finish scans the block sums -> g_boff, writes the
// sentinel, and resets the ticket. off(i) = g_off[i] + g_boff[i>>10].
__global__ void __launch_bounds__(SCAN_BLK) scan_kernel(int n, int n_nodes) {
    __shared__ int warp_sums[32];
    __shared__ int s_last;
    const int t = threadIdx.x;
    const int i = blockIdx.x * SCAN_BLK + t;
    const int lane = t & 31;
    const int wid  = t >> 5;

    int v = (i < n) ? g_deg[i] : 0;

    int incl = v;
    #pragma unroll
    for (int d = 1; d < 32; d <<= 1) {
        int y = __shfl_up_sync(0xffffffffu, incl, d);
        if (lane >= d) incl += y;
    }
    if (lane == 31) warp_sums[wid] = incl;
    __syncthreads();

    if (wid == 0) {
        int s = warp_sums[lane];
        #pragma unroll
        for (int d = 1; d < 32; d <<= 1) {
            int y = __shfl_up_sync(0xffffffffu, s, d);
            if (lane >= d) s += y;
        }
        warp_sums[lane] = s;
    }
    __syncthreads();

    int woff = (wid > 0) ? warp_sums[wid - 1] : 0;
    if (i < n) g_off[i] = woff + incl - v;
    if (t == SCAN_BLK - 1) g_bsum[blockIdx.x] = woff + incl;

    __threadfence();
    if (t == 0) {
        int c = atomicAdd(&g_scan_done, 1);
        s_last = (c == (int)gridDim.x - 1) ? 1 : 0;
    }
    __syncthreads();

    if (s_last) {
        __threadfence();
        const int nblk = (int)gridDim.x;
        int bv = 0, bincl = 0;
        if (t < 128) {
            bv = (t < nblk) ? g_bsum[t] : 0;
            bincl = bv;
            #pragma unroll
            for (int d = 1; d < 32; d <<= 1) {
                int y = __shfl_up_sync(0xffffffffu, bincl, d);
                if (lane >= d) bincl += y;
            }
            if (lane == 31) warp_sums[wid] = bincl;
        }
        __syncthreads();
        if (t < 128) {
            int pre = 0;
            #pragma unroll
            for (int w = 0; w < 4; w++)
                if (w < wid) pre += warp_sums[w];
            if (t < nblk) g_boff[t] = pre + bincl - bv;   // exclusive
            if (t == nblk - 1) g_off[n_nodes] = bv;       // sentinel
        }
        if (t == 0) g_scan_done = 0;
    }
}

// fill (atomic-free via precomputed ranks) + re-zero g_deg for the next call
__global__ void __launch_bounds__(256) fill_kernel(
    const int* __restrict__ src, const int* __restrict__ dst,
    int n_edges, int n_nodes)
{
    const int tid    = blockIdx.x * blockDim.x + threadIdx.x;
    const int stride = gridDim.x * blockDim.x;
    const int n4     = n_edges >> 2;

    for (int e4 = tid; e4 < n4; e4 += stride) {
        const int4 s = reinterpret_cast<const int4*>(src)[e4];
        const int4 d = reinterpret_cast<const int4*>(dst)[e4];
        const int4 r = reinterpret_cast<const int4*>(g_rank)[e4];
        g_edge_src[__ldg(&g_off[d.x]) + __ldg(&g_boff[d.x >> 10]) + r.x] = s.x;
        g_edge_src[__ldg(&g_off[d.y]) + __ldg(&g_boff[d.y >> 10]) + r.y] = s.y;
        g_edge_src[__ldg(&g_off[d.z]) + __ldg(&g_boff[d.z >> 10]) + r.z] = s.z;
        g_edge_src[__ldg(&g_off[d.w]) + __ldg(&g_boff[d.w >> 10]) + r.w] = s.w;
    }
    for (int e = (n4 << 2) + tid; e < n_edges; e += stride)
        g_edge_src[__ldg(&g_off[dst[e]]) + __ldg(&g_boff[dst[e] >> 10])
                   + g_rank[e]] = src[e];

    for (int i = tid; i < n_nodes; i += stride)
        g_deg[i] = 0;
}

// ---------------------------------------------------------------------------
// gather: full-width aggregate of fp16 Y + bias + ReLU -> fp32 out.
// Warp per node; lane owns 4 contiguous feats (uint2 = 8 B; 256 B/warp
// coalesced). fp32 accumulation. Compact unroll-4 loop (R11 — best known).
// ---------------------------------------------------------------------------
__global__ void __launch_bounds__(256) gather_epi_kernel(
    const float* __restrict__ bias,
    float* __restrict__ out,
    int n_nodes)
{
    const int lane    = threadIdx.x & 31;
    const int warp    = (blockIdx.x * blockDim.x + threadIdx.x) >> 5;
    const int n_warps = (gridDim.x * blockDim.x) >> 5;

    const float4 bv = *reinterpret_cast<const float4*>(bias + lane * 4);

    for (int n = warp; n < n_nodes; n += n_warps) {
        const int beg = __ldg(&g_off[n])     + __ldg(&g_boff[n >> 10]);
        const int end = __ldg(&g_off[n + 1]) + __ldg(&g_boff[(n + 1) >> 10]);

        float4 acc = make_float4(0.f, 0.f, 0.f, 0.f);

        for (int i = beg; i < end; i += 32) {
            const int cnt = min(32, end - i);
            int s = (lane < cnt) ? g_edge_src[i + lane] : 0;
            #pragma unroll 4
            for (int j = 0; j < cnt; j++) {
                const int sj = __shfl_sync(0xffffffffu, s, j);
                const uint2 v = *reinterpret_cast<const uint2*>(
                    g_y + (size_t)sj * N_FEATS + lane * 4);
                const float2 f0 =
                    __half22float2(*reinterpret_cast<const __half2*>(&v.x));
                const float2 f1 =
                    __half22float2(*reinterpret_cast<const __half2*>(&v.y));
                acc.x += f0.x; acc.y += f0.y; acc.z += f1.x; acc.w += f1.y;
            }
        }

        float4 o;
        o.x = fmaxf(acc.x + bv.x, 0.f);
        o.y = fmaxf(acc.y + bv.y, 0.f);
        o.z = fmaxf(acc.z + bv.z, 0.f);
        o.w = fmaxf(acc.w + bv.w, 0.f);
        *reinterpret_cast<float4*>(out + (size_t)n * N_FEATS + lane * 4) = o;
    }
}

// ---------------------------------------------------------------------------
extern "C" void kernel_launch(void* const* d_in, const int* in_sizes, int n_in,
                              void* d_out, int out_size)
{
    const float* feat = (const float*)d_in[0];
    const int*   src  = (const int*)d_in[1];
    const int*   dst  = (const int*)d_in[2];
    const float* W    = (const float*)d_in[3];
    const float* bias = (const float*)d_in[4];
    float*       out  = (float*)d_out;

    const int n_edges = in_sizes[1];
    const int M       = in_sizes[0] / N_FEATS;   // 100000 nodes
    const int nblk    = (M + SCAN_BLK - 1) / SCAN_BLK;

    cudaStream_t s2;
    cudaStreamCreateWithFlags(&s2, cudaStreamNonBlocking);
    cudaEvent_t ev_fork, ev_join;
    cudaEventCreateWithFlags(&ev_fork, cudaEventDisableTiming);
    cudaEventCreateWithFlags(&ev_join, cudaEventDisableTiming);

    // fork: W pre-split, then tensor-core GEMM (overlaps CSR build)
    cudaEventRecord(ev_fork, 0);
    cudaStreamWaitEvent(s2, ev_fork, 0);
    wsplit_kernel<<<32, 256, 0, s2>>>(W);
    gemm_mma_kernel<<<(M + 127) / 128, 256, 0, s2>>>(feat, M);
    cudaEventRecord(ev_join, s2);

    // main stream: CSR build (g_deg arrives zeroed: static init / prev fill)
    hist_rank_kernel<<<1184, 256>>>(dst, n_edges);
    scan_kernel<<<nblk, SCAN_BLK>>>(M, M);
    fill_kernel<<<1184, 256>>>(src, dst, n_edges, M);

    // join, then gather + bias + ReLU
    cudaStreamWaitEvent(0, ev_join, 0);
    gather_epi_kernel<<<1184, 256>>>(bias, out, M);

    cudaEventDestroy(ev_fork);
    cudaEventDestroy(ev_join);
    cudaStreamDestroy(s2);
}

// round 14
// speedup vs baseline: 1.2819x; 1.2819x over previous
#include <cuda_runtime.h>
#include <cuda_bf16.h>
#include <cuda_fp16.h>
#include <cstdint>

// GCN layer: out = ReLU( segment_sum(feature[src], dst) @ W^T + b )
// N=100000, E=1.6M, 128 feats, fp32. src/dst int32.
//
// R14 = R11 (fp16 Y, GEMM fork, warp-per-node unroll-4 gather, single-pass
// scan, no memset) with the GEMM switched from 3-combo bf16-split to a
// SINGLE fp16 m16n8k16 MMA (fp32 accum). Y is already fp16 (2^-11), so
// fp16 GEMM inputs add same-order error: predicted total ~4e-4 < 1e-3.
// 3x fewer MMAs, split2 ALU -> one cvt per pair.

#define N_FEATS   128
#define MAX_NODES 100000
#define MAX_EDGES 1600000
#define SCAN_BLK  1024
#define N_SCAN_BLKS ((MAX_NODES + SCAN_BLK - 1) / SCAN_BLK)   // 98

__device__ __half g_y[MAX_NODES * N_FEATS];    // Y = feat @ W^T (fp16)
__device__ int    g_deg[MAX_NODES];            // zero on entry (static/fill)
__device__ int    g_off[MAX_NODES + 1];
__device__ int    g_bsum[N_SCAN_BLKS];
__device__ int    g_boff[N_SCAN_BLKS];
__device__ int    g_rank[MAX_EDGES];
__device__ int    g_edge_src[MAX_EDGES];
__device__ int    g_scan_done;                 // ticket; reset by last block

#define MMA16816F16(d, a, b)                                                  \
    asm volatile(                                                             \
        "mma.sync.aligned.m16n8k16.row.col.f32.f16.f16.f32 "                 \
        "{%0,%1,%2,%3}, {%4,%5,%6,%7}, {%8,%9}, {%0,%1,%2,%3};"              \
        : "+f"((d)[0]), "+f"((d)[1]), "+f"((d)[2]), "+f"((d)[3])              \
        : "r"((a)[0]), "r"((a)[1]), "r"((a)[2]), "r"((a)[3]),                 \
          "r"((b)[0]), "r"((b)[1]))

__device__ __forceinline__ uint32_t pack_h2(float a, float b) {
    const __half2 h = __floats2half2_rn(a, b);
    return *reinterpret_cast<const uint32_t*>(&h);
}

// ---------------------------------------------------------------------------
// GEMM: Y = feat @ W^T (fp16 out). Block 256 thr; tile 128 rows x 128 cols.
// fp16 inputs, single MMA per (mt,nt,ks), fp32 accum.
// ---------------------------------------------------------------------------
__global__ void __launch_bounds__(256) gemm_mma_kernel(
    const float* __restrict__ feat,   // [M, 128]
    const float* __restrict__ W,      // [128, 128] row-major: W[n][k]
    int M)
{
    const int tid  = threadIdx.x;
    const int wid  = tid >> 5;
    const int lane = tid & 31;
    const int g    = lane >> 2;
    const int t    = lane & 3;

    const int rbase = blockIdx.x * 128 + (wid >> 1) * 32;
    const int cbase = (wid & 1) * 64;

    const float* arow[2][2];
    #pragma unroll
    for (int mt = 0; mt < 2; mt++) {
        int rlo = rbase + mt * 16 + g;
        int rhi = rlo + 8;
        if (rlo > M - 1) rlo = M - 1;
        if (rhi > M - 1) rhi = M - 1;
        arow[mt][0] = feat + (size_t)rlo * N_FEATS;
        arow[mt][1] = feat + (size_t)rhi * N_FEATS;
    }

    float acc[2][8][4];
    #pragma unroll
    for (int mt = 0; mt < 2; mt++)
        #pragma unroll
        for (int nt = 0; nt < 8; nt++)
            #pragma unroll
            for (int q = 0; q < 4; q++)
                acc[mt][nt][q] = 0.f;

    #pragma unroll 2
    for (int ks = 0; ks < 8; ks++) {
        const int k0 = ks * 16;

        uint32_t A[2][4];
        #pragma unroll
        for (int mt = 0; mt < 2; mt++) {
            const float2 a0 = *reinterpret_cast<const float2*>(
                arow[mt][0] + k0 + 2 * t);
            const float2 a1 = *reinterpret_cast<const float2*>(
                arow[mt][1] + k0 + 2 * t);
            const float2 a2 = *reinterpret_cast<const float2*>(
                arow[mt][0] + k0 + 2 * t + 8);
            const float2 a3 = *reinterpret_cast<const float2*>(
                arow[mt][1] + k0 + 2 * t + 8);
            A[mt][0] = pack_h2(a0.x, a0.y);
            A[mt][1] = pack_h2(a1.x, a1.y);
            A[mt][2] = pack_h2(a2.x, a2.y);
            A[mt][3] = pack_h2(a3.x, a3.y);
        }

        #pragma unroll
        for (int nt = 0; nt < 8; nt++) {
            const int n = cbase + nt * 8 + g;
            const float2 b0 = *reinterpret_cast<const float2*>(
                W + (size_t)n * N_FEATS + k0 + 2 * t);
            const float2 b1 = *reinterpret_cast<const float2*>(
                W + (size_t)n * N_FEATS + k0 + 2 * t + 8);
            uint32_t B[2];
            B[0] = pack_h2(b0.x, b0.y);
            B[1] = pack_h2(b1.x, b1.y);

            #pragma unroll
            for (int mt = 0; mt < 2; mt++)
                MMA16816F16(acc[mt][nt], A[mt], B);
        }
    }

    #pragma unroll
    for (int mt = 0; mt < 2; mt++) {
        const int rlo = rbase + mt * 16 + g;
        const int rhi = rlo + 8;
        #pragma unroll
        for (int nt = 0; nt < 8; nt++) {
            const int col = cbase + nt * 8 + 2 * t;
            if (rlo < M)
                *reinterpret_cast<__half2*>(g_y + (size_t)rlo * N_FEATS + col) =
                    __floats2half2_rn(acc[mt][nt][0], acc[mt][nt][1]);
            if (rhi < M)
                *reinterpret_cast<__half2*>(g_y + (size_t)rhi * N_FEATS + col) =
                    __floats2half2_rn(acc[mt][nt][2], acc[mt][nt][3]);
        }
    }
}

// ======================= CSR build =========================================
__global__ void __launch_bounds__(256) hist_rank_kernel(
    const int* __restrict__ dst, int n_edges)
{
    const int tid    = blockIdx.x * blockDim.x + threadIdx.x;
    const int stride = gridDim.x * blockDim.x;
    const int n4     = n_edges >> 2;

    for (int e4 = tid; e4 < n4; e4 += stride) {
        const int4 d = reinterpret_cast<const int4*>(dst)[e4];
        int4 r;
        r.x = atomicAdd(&g_deg[d.x], 1);
        r.y = atomicAdd(&g_deg[d.y], 1);
        r.z = atomicAdd(&g_deg[d.z], 1);
        r.w = atomicAdd(&g_deg[d.w], 1);
        reinterpret_cast<int4*>(g_rank)[e4] = r;
    }
    for (int e = (n4 << 2) + tid; e < n_edges; e += stride)
        g_rank[e] = atomicAdd(&g_deg[dst[e]], 1);
}

// single-pass scan: per-block exclusive scan of g_deg -> g_off + block sums;
// the LAST block to finish scans the block sums -> g_boff, writes the
// sentinel, and resets the ticket. off(i) = g_off[i] + g_boff[i>>10].
__global__ void __launch_bounds__(SCAN_BLK) scan_kernel(int n, int n_nodes) {
    __shared__ int warp_sums[32];
    __shared__ int s_last;
    const int t = threadIdx.x;
    const int i = blockIdx.x * SCAN_BLK + t;
    const int lane = t & 31;
    const int wid  = t >> 5;

    int v = (i < n) ? g_deg[i] : 0;

    int incl = v;
    #pragma unroll
    for (int d = 1; d < 32; d <<= 1) {
        int y = __shfl_up_sync(0xffffffffu, incl, d);
        if (lane >= d) incl += y;
    }
    if (lane == 31) warp_sums[wid] = incl;
    __syncthreads();

    if (wid == 0) {
        int s = warp_sums[lane];
        #pragma unroll
        for (int d = 1; d < 32; d <<= 1) {
            int y = __shfl_up_sync(0xffffffffu, s, d);
            if (lane >= d) s += y;
        }
        warp_sums[lane] = s;
    }
    __syncthreads();

    int woff = (wid > 0) ? warp_sums[wid - 1] : 0;
    if (i < n) g_off[i] = woff + incl - v;
    if (t == SCAN_BLK - 1) g_bsum[blockIdx.x] = woff + incl;

    __threadfence();
    if (t == 0) {
        int c = atomicAdd(&g_scan_done, 1);
        s_last = (c == (int)gridDim.x - 1) ? 1 : 0;
    }
    __syncthreads();

    if (s_last) {
        __threadfence();
        const int nblk = (int)gridDim.x;
        int bv = 0, bincl = 0;
        if (t < 128) {
            bv = (t < nblk) ? g_bsum[t] : 0;
            bincl = bv;
            #pragma unroll
            for (int d = 1; d < 32; d <<= 1) {
                int y = __shfl_up_sync(0xffffffffu, bincl, d);
                if (lane >= d) bincl += y;
            }
            if (lane == 31) warp_sums[wid] = bincl;
        }
        __syncthreads();
        if (t < 128) {
            int pre = 0;
            #pragma unroll
            for (int w = 0; w < 4; w++)
                if (w < wid) pre += warp_sums[w];
            if (t < nblk) g_boff[t] = pre + bincl - bv;   // exclusive
            if (t == nblk - 1) g_off[n_nodes] = bv;       // sentinel
        }
        if (t == 0) g_scan_done = 0;
    }
}

// fill (atomic-free via precomputed ranks) + re-zero g_deg for the next call
__global__ void __launch_bounds__(256) fill_kernel(
    const int* __restrict__ src, const int* __restrict__ dst,
    int n_edges, int n_nodes)
{
    const int tid    = blockIdx.x * blockDim.x + threadIdx.x;
    const int stride = gridDim.x * blockDim.x;
    const int n4     = n_edges >> 2;

    for (int e4 = tid; e4 < n4; e4 += stride) {
        const int4 s = reinterpret_cast<const int4*>(src)[e4];
        const int4 d = reinterpret_cast<const int4*>(dst)[e4];
        const int4 r = reinterpret_cast<const int4*>(g_rank)[e4];
        g_edge_src[__ldg(&g_off[d.x]) + __ldg(&g_boff[d.x >> 10]) + r.x] = s.x;
        g_edge_src[__ldg(&g_off[d.y]) + __ldg(&g_boff[d.y >> 10]) + r.y] = s.y;
        g_edge_src[__ldg(&g_off[d.z]) + __ldg(&g_boff[d.z >> 10]) + r.z] = s.z;
        g_edge_src[__ldg(&g_off[d.w]) + __ldg(&g_boff[d.w >> 10]) + r.w] = s.w;
    }
    for (int e = (n4 << 2) + tid; e < n_edges; e += stride)
        g_edge_src[__ldg(&g_off[dst[e]]) + __ldg(&g_boff[dst[e] >> 10])
                   + g_rank[e]] = src[e];

    for (int i = tid; i < n_nodes; i += stride)
        g_deg[i] = 0;
}

// ---------------------------------------------------------------------------
// gather: full-width aggregate of fp16 Y + bias + ReLU -> fp32 out.
// Warp per node; lane owns 4 contiguous feats (uint2 = 8 B; 256 B/warp
// coalesced). fp32 accumulation. Compact unroll-4 loop (R11 — best known).
// ---------------------------------------------------------------------------
__global__ void __launch_bounds__(256) gather_epi_kernel(
    const float* __restrict__ bias,
    float* __restrict__ out,
    int n_nodes)
{
    const int lane    = threadIdx.x & 31;
    const int warp    = (blockIdx.x * blockDim.x + threadIdx.x) >> 5;
    const int n_warps = (gridDim.x * blockDim.x) >> 5;

    const float4 bv = *reinterpret_cast<const float4*>(bias + lane * 4);

    for (int n = warp; n < n_nodes; n += n_warps) {
        const int beg = __ldg(&g_off[n])     + __ldg(&g_boff[n >> 10]);
        const int end = __ldg(&g_off[n + 1]) + __ldg(&g_boff[(n + 1) >> 10]);

        float4 acc = make_float4(0.f, 0.f, 0.f, 0.f);

        for (int i = beg; i < end; i += 32) {
            const int cnt = min(32, end - i);
            int s = (lane < cnt) ? g_edge_src[i + lane] : 0;
            #pragma unroll 4
            for (int j = 0; j < cnt; j++) {
                const int sj = __shfl_sync(0xffffffffu, s, j);
                const uint2 v = *reinterpret_cast<const uint2*>(
                    g_y + (size_t)sj * N_FEATS + lane * 4);
                const float2 f0 =
                    __half22float2(*reinterpret_cast<const __half2*>(&v.x));
                const float2 f1 =
                    __half22float2(*reinterpret_cast<const __half2*>(&v.y));
                acc.x += f0.x; acc.y += f0.y; acc.z += f1.x; acc.w += f1.y;
            }
        }

        float4 o;
        o.x = fmaxf(acc.x + bv.x, 0.f);
        o.y = fmaxf(acc.y + bv.y, 0.f);
        o.z = fmaxf(acc.z + bv.z, 0.f);
        o.w = fmaxf(acc.w + bv.w, 0.f);
        *reinterpret_cast<float4*>(out + (size_t)n * N_FEATS + lane * 4) = o;
    }
}

// ---------------------------------------------------------------------------
extern "C" void kernel_launch(void* const* d_in, const int* in_sizes, int n_in,
                              void* d_out, int out_size)
{
    const float* feat = (const float*)d_in[0];
    const int*   src  = (const int*)d_in[1];
    const int*   dst  = (const int*)d_in[2];
    const float* W    = (const float*)d_in[3];
    const float* bias = (const float*)d_in[4];
    float*       out  = (float*)d_out;

    const int n_edges = in_sizes[1];
    const int M       = in_sizes[0] / N_FEATS;   // 100000 nodes
    const int nblk    = (M + SCAN_BLK - 1) / SCAN_BLK;

    cudaStream_t s2;
    cudaStreamCreateWithFlags(&s2, cudaStreamNonBlocking);
    cudaEvent_t ev_fork, ev_join;
    cudaEventCreateWithFlags(&ev_fork, cudaEventDisableTiming);
    cudaEventCreateWithFlags(&ev_join, cudaEventDisableTiming);

    // fork tensor-core GEMM (overlaps CSR build)
    cudaEventRecord(ev_fork, 0);
    cudaStreamWaitEvent(s2, ev_fork, 0);
    gemm_mma_kernel<<<(M + 127) / 128, 256, 0, s2>>>(feat, W, M);
    cudaEventRecord(ev_join, s2);

    // main stream: CSR build (g_deg arrives zeroed: static init / prev fill)
    hist_rank_kernel<<<1184, 256>>>(dst, n_edges);
    scan_kernel<<<nblk, SCAN_BLK>>>(M, M);
    fill_kernel<<<1184, 256>>>(src, dst, n_edges, M);

    // join, then gather + bias + ReLU
    cudaStreamWaitEvent(0, ev_join, 0);
    gather_epi_kernel<<<1184, 256>>>(bias, out, M);

    cudaEventDestroy(ev_fork);
    cudaEventDestroy(ev_join);
    cudaStreamDestroy(s2);
}